// round 5
// baseline (speedup 1.0000x reference)
#include <cuda_runtime.h>
#include <cuda_bf16.h>
#include <math_constants.h>

// Problem constants (fixed-shape benchmark)
#define Bsz 2048
#define Tsz 512
#define Ksz 8
#define Dsz 8
#define NV  28          // D*(D-1)/2
#define PSTRIDE 92      // floats per (t,k): Q[64] ctr[8] c[8] bco[8] w[1] pad[3]

#define EPSV 1e-7f
#define GAIN 3.5f
#define MAXLV 3.5f

// Precomputed per-(t,k) parameters: 4096 * 92 * 4B = 1.5 MB scratch
__device__ float g_params[Tsz * Ksz * PSTRIDE];

// ---------------------------------------------------------------------------
// Kernel 1: per-(t,k) precompute.
//   Q = (I - A)(I + A)^{-1} = 2*(I+A)^{-1} - I    (A antisymmetric)
//   (I+A) has SPD symmetric part (=I) -> Gauss-Jordan without pivoting is safe.
// Also precomputes per-dim  c = 1/sqrt(2*pi*var),  bco = 0.5/var,
// and the softmax weight for this (t,k).
// ---------------------------------------------------------------------------
__global__ void __launch_bounds__(256)
precompute_kernel(const float* __restrict__ centers,
                  const float* __restrict__ wlogits,
                  const float* __restrict__ logvar,
                  const float* __restrict__ covp)
{
    int id = blockIdx.x * blockDim.x + threadIdx.x;
    if (id >= Tsz * Ksz) return;
    int t = id / Ksz;
    int k = id - t * Ksz;

    const float* v = covp + id * NV;

    // M = I + A, where (for i<j, f = 8*i+j):
    //   UT[i][j] = (f < 28) ? v[f] : v[55 - f]
    //   A[i][j] = -0.5*UT[i][j],  A[j][i] = +0.5*UT[i][j]
    float M[Dsz][Dsz];
    float Inv[Dsz][Dsz];
#pragma unroll
    for (int i = 0; i < Dsz; i++)
#pragma unroll
        for (int j = 0; j < Dsz; j++) {
            M[i][j]   = (i == j) ? 1.0f : 0.0f;
            Inv[i][j] = (i == j) ? 1.0f : 0.0f;
        }
#pragma unroll
    for (int i = 0; i < Dsz; i++) {
#pragma unroll
        for (int j = i + 1; j < Dsz; j++) {
            int f = 8 * i + j;
            float u = (f < NV) ? v[f] : v[55 - f];
            M[i][j] -= 0.5f * u;
            M[j][i] += 0.5f * u;
        }
    }

    // Gauss-Jordan inversion (no pivoting needed)
#pragma unroll
    for (int col = 0; col < Dsz; col++) {
        float piv = 1.0f / M[col][col];
#pragma unroll
        for (int j = 0; j < Dsz; j++) {
            M[col][j]   *= piv;
            Inv[col][j] *= piv;
        }
#pragma unroll
        for (int r = 0; r < Dsz; r++) {
            if (r == col) continue;
            float f2 = M[r][col];
#pragma unroll
            for (int j = 0; j < Dsz; j++) {
                M[r][j]   = fmaf(-f2, M[col][j],   M[r][j]);
                Inv[r][j] = fmaf(-f2, Inv[col][j], Inv[r][j]);
            }
        }
    }

    float* P = g_params + (size_t)id * PSTRIDE;

    // Q = 2*Inv - I, stored row-major [i][j]
#pragma unroll
    for (int i = 0; i < Dsz; i++)
#pragma unroll
        for (int j = 0; j < Dsz; j++)
            P[i * 8 + j] = 2.0f * Inv[i][j] - ((i == j) ? 1.0f : 0.0f);

#pragma unroll
    for (int d = 0; d < Dsz; d++) {
        P[64 + d] = centers[id * Dsz + d];
        float lv = logvar[id * Dsz + d];
        lv = fminf(fmaxf(lv, -MAXLV), MAXLV);
        float var = expf(lv);
        P[72 + d] = rsqrtf(2.0f * CUDART_PI_F * var);  // norm coeff c
        P[80 + d] = 0.5f / var;                        // bco
    }

    // softmax weight over K for this t (clipped logits)
    const float* wl = wlogits + t * Ksz;
    float cl[Ksz];
    float mx = -1e30f;
#pragma unroll
    for (int kk = 0; kk < Ksz; kk++) {
        cl[kk] = fminf(fmaxf(wl[kk], -GAIN), GAIN);
        mx = fmaxf(mx, cl[kk]);
    }
    float sum = 0.0f;
#pragma unroll
    for (int kk = 0; kk < Ksz; kk++) sum += expf(cl[kk] - mx);
    P[88] = expf(cl[k] - mx) / sum;
    P[89] = 0.0f; P[90] = 0.0f; P[91] = 0.0f;
}

// ---------------------------------------------------------------------------
// Kernel 2: main evaluation. One thread per (b,t).
// Block = 256 threads over b, one t per block (params in smem, broadcast LDS).
//
// Per (b,t,k):
//   xc = x - ctr
//   xt_j = sum_i xc_i * Q[i][j]
//   p_k  = prod_d ( c_d * exp(-bco_d * xt_d^2) + EPS )   [== exp(sum log(g+eps))]
//   p   += w_k * p_k
// ---------------------------------------------------------------------------
__global__ void __launch_bounds__(256)
main_kernel(const float* __restrict__ x, float* __restrict__ out)
{
    const int t = blockIdx.y;
    const int b = blockIdx.x * 256 + threadIdx.x;

    __shared__ float sp[Ksz * PSTRIDE];
    const float* gp = g_params + (size_t)t * Ksz * PSTRIDE;
#pragma unroll
    for (int i = threadIdx.x; i < Ksz * PSTRIDE; i += 256)
        sp[i] = gp[i];
    __syncthreads();

    if (b >= Bsz) return;

    // x[b][t][0..7] : 32 bytes, 16B-aligned
    const float4* xp = reinterpret_cast<const float4*>(x + ((size_t)b * Tsz + t) * Dsz);
    float4 xa = xp[0];
    float4 xb = xp[1];
    float xv[Dsz] = {xa.x, xa.y, xa.z, xa.w, xb.x, xb.y, xb.z, xb.w};

    float p = 0.0f;

#pragma unroll
    for (int k = 0; k < Ksz; k++) {
        const float* P = sp + k * PSTRIDE;

        float xc[Dsz];
#pragma unroll
        for (int i = 0; i < Dsz; i++)
            xc[i] = xv[i] - P[64 + i];

        float xt[Dsz];
#pragma unroll
        for (int j = 0; j < Dsz; j++) xt[j] = 0.0f;

#pragma unroll
        for (int i = 0; i < Dsz; i++) {
            float4 qa = *reinterpret_cast<const float4*>(P + i * 8);
            float4 qb = *reinterpret_cast<const float4*>(P + i * 8 + 4);
            xt[0] = fmaf(xc[i], qa.x, xt[0]);
            xt[1] = fmaf(xc[i], qa.y, xt[1]);
            xt[2] = fmaf(xc[i], qa.z, xt[2]);
            xt[3] = fmaf(xc[i], qa.w, xt[3]);
            xt[4] = fmaf(xc[i], qb.x, xt[4]);
            xt[5] = fmaf(xc[i], qb.y, xt[5]);
            xt[6] = fmaf(xc[i], qb.z, xt[6]);
            xt[7] = fmaf(xc[i], qb.w, xt[7]);
        }

        float4 ca = *reinterpret_cast<const float4*>(P + 72);
        float4 cb = *reinterpret_cast<const float4*>(P + 76);
        float4 ba = *reinterpret_cast<const float4*>(P + 80);
        float4 bb = *reinterpret_cast<const float4*>(P + 84);
        const float cc[Dsz] = {ca.x, ca.y, ca.z, ca.w, cb.x, cb.y, cb.z, cb.w};
        const float bc[Dsz] = {ba.x, ba.y, ba.z, ba.w, bb.x, bb.y, bb.z, bb.w};

        float pk = 1.0f;
#pragma unroll
        for (int j = 0; j < Dsz; j++) {
            float s = xt[j] * xt[j] * bc[j];
            float g = fmaf(cc[j], __expf(-s), EPSV);   // c*exp(-h) + eps
            pk *= g;
        }

        p = fmaf(P[88], pk, p);
    }

    out[(size_t)b * Tsz + t] = p;
}

// ---------------------------------------------------------------------------
// Launch
// ---------------------------------------------------------------------------
extern "C" void kernel_launch(void* const* d_in, const int* in_sizes, int n_in,
                              void* d_out, int out_size)
{
    const float* x       = (const float*)d_in[0];   // [B,T,D]
    const float* centers = (const float*)d_in[1];   // [T,K,D]
    const float* wlogits = (const float*)d_in[2];   // [T,K]
    const float* logvar  = (const float*)d_in[3];   // [T,K,D]
    const float* covp    = (const float*)d_in[4];   // [T,K,28]
    float* out = (float*)d_out;                     // [B,T]

    precompute_kernel<<<(Tsz * Ksz + 255) / 256, 256>>>(centers, wlogits, logvar, covp);

    dim3 grid((Bsz + 255) / 256, Tsz);
    main_kernel<<<grid, 256>>>(x, out);
}

// round 10
// speedup vs baseline: 1.3583x; 1.3583x over previous
#include <cuda_runtime.h>
#include <cuda_bf16.h>
#include <math_constants.h>

// Problem constants (fixed-shape benchmark)
#define Bsz 2048
#define Tsz 512
#define Ksz 8
#define Dsz 8
#define NV  28          // D*(D-1)/2
#define PSTRIDE 92      // floats per (t,k): Q[64] ctr[8] lc[8] nb[8] w[1] pad[3]
#define ITEMS 4
#define MTHREADS 128

#define EPSV 1e-7f
#define GAIN 3.5f
#define MAXLV 3.5f
#define LOG2E 1.4426950408889634f

// Precomputed per-(t,k) parameters: 4096 * 92 * 4B = 1.5 MB scratch
__device__ float g_params[Tsz * Ksz * PSTRIDE];

__device__ __forceinline__ float ex2(float v) {
    float r;
    asm("ex2.approx.ftz.f32 %0, %1;" : "=f"(r) : "f"(v));
    return r;
}

// ---------------------------------------------------------------------------
// Kernel 1: per-(t,k) precompute.
//   Q = (I - A)(I + A)^{-1} = 2*(I+A)^{-1} - I    (A antisymmetric)
//   Gauss-Jordan without pivoting is safe (symmetric part of I+A is I).
// Stores per-dim  lc = log2(1/sqrt(2*pi*var)),  nb = -0.5*log2(e)/var,
// and the softmax weight.
// Launched with block=32 so the 128 blocks spread across SMs (latency-bound).
// ---------------------------------------------------------------------------
__global__ void __launch_bounds__(32)
precompute_kernel(const float* __restrict__ centers,
                  const float* __restrict__ wlogits,
                  const float* __restrict__ logvar,
                  const float* __restrict__ covp)
{
    int id = blockIdx.x * blockDim.x + threadIdx.x;
    if (id >= Tsz * Ksz) return;
    int t = id / Ksz;
    int k = id - t * Ksz;

    const float* v = covp + id * NV;

    float M[Dsz][Dsz];
    float Inv[Dsz][Dsz];
#pragma unroll
    for (int i = 0; i < Dsz; i++)
#pragma unroll
        for (int j = 0; j < Dsz; j++) {
            M[i][j]   = (i == j) ? 1.0f : 0.0f;
            Inv[i][j] = (i == j) ? 1.0f : 0.0f;
        }
#pragma unroll
    for (int i = 0; i < Dsz; i++) {
#pragma unroll
        for (int j = i + 1; j < Dsz; j++) {
            int f = 8 * i + j;
            float u = (f < NV) ? v[f] : v[55 - f];
            M[i][j] -= 0.5f * u;
            M[j][i] += 0.5f * u;
        }
    }

#pragma unroll
    for (int col = 0; col < Dsz; col++) {
        float piv = 1.0f / M[col][col];
#pragma unroll
        for (int j = 0; j < Dsz; j++) {
            M[col][j]   *= piv;
            Inv[col][j] *= piv;
        }
#pragma unroll
        for (int r = 0; r < Dsz; r++) {
            if (r == col) continue;
            float f2 = M[r][col];
#pragma unroll
            for (int j = 0; j < Dsz; j++) {
                M[r][j]   = fmaf(-f2, M[col][j],   M[r][j]);
                Inv[r][j] = fmaf(-f2, Inv[col][j], Inv[r][j]);
            }
        }
    }

    float* P = g_params + (size_t)id * PSTRIDE;

    // Q = 2*Inv - I, row-major [i][j]
#pragma unroll
    for (int i = 0; i < Dsz; i++)
#pragma unroll
        for (int j = 0; j < Dsz; j++)
            P[i * 8 + j] = 2.0f * Inv[i][j] - ((i == j) ? 1.0f : 0.0f);

#pragma unroll
    for (int d = 0; d < Dsz; d++) {
        P[64 + d] = centers[id * Dsz + d];
        float lv = logvar[id * Dsz + d];
        lv = fminf(fmaxf(lv, -MAXLV), MAXLV);
        float var = expf(lv);
        float c = rsqrtf(2.0f * CUDART_PI_F * var);
        P[72 + d] = log2f(c);            // lc
        P[80 + d] = -0.5f * LOG2E / var; // nb
    }

    const float* wl = wlogits + t * Ksz;
    float cl[Ksz];
    float mx = -1e30f;
#pragma unroll
    for (int kk = 0; kk < Ksz; kk++) {
        cl[kk] = fminf(fmaxf(wl[kk], -GAIN), GAIN);
        mx = fmaxf(mx, cl[kk]);
    }
    float sum = 0.0f;
#pragma unroll
    for (int kk = 0; kk < Ksz; kk++) sum += expf(cl[kk] - mx);
    P[88] = expf(cl[k] - mx) / sum;
    P[89] = 0.0f; P[90] = 0.0f; P[91] = 0.0f;
}

// ---------------------------------------------------------------------------
// Kernel 2: main evaluation. Each thread handles ITEMS=4 b-values for one t,
// so every LDS of Q / coefficients is reused 4x from registers (the smem
// crossbar return path was the R4 bottleneck: broadcast LDS.128 still pays
// 16B per LANE on the return wavefronts).
//
// Per (b,t,k):
//   xc = x - ctr ; xt = xc * Q
//   p_k = prod_d ( 2^(lc_d + nb_d*xt_d^2) + EPS )
//   p  += w_k * p_k
// ---------------------------------------------------------------------------
__global__ void __launch_bounds__(MTHREADS)
main_kernel(const float* __restrict__ x, float* __restrict__ out)
{
    const int t = blockIdx.y;
    const int tid = threadIdx.x;

    __shared__ float sp[Ksz * PSTRIDE];
    const float* gp = g_params + (size_t)t * Ksz * PSTRIDE;
    for (int i = tid; i < Ksz * PSTRIDE; i += MTHREADS)
        sp[i] = gp[i];
    __syncthreads();

    const int b0 = blockIdx.x * (MTHREADS * ITEMS) + tid;

    // Load x for all items: x[b][t][0..7] (32B, 16B-aligned)
    float xv[ITEMS][Dsz];
#pragma unroll
    for (int it = 0; it < ITEMS; it++) {
        int b = b0 + it * MTHREADS;
        const float4* xp = reinterpret_cast<const float4*>(x + ((size_t)b * Tsz + t) * Dsz);
        float4 xa = xp[0];
        float4 xb = xp[1];
        xv[it][0] = xa.x; xv[it][1] = xa.y; xv[it][2] = xa.z; xv[it][3] = xa.w;
        xv[it][4] = xb.x; xv[it][5] = xb.y; xv[it][6] = xb.z; xv[it][7] = xb.w;
    }

    float acc[ITEMS];
#pragma unroll
    for (int it = 0; it < ITEMS; it++) acc[it] = 0.0f;

#pragma unroll
    for (int k = 0; k < Ksz; k++) {
        const float* P = sp + k * PSTRIDE;

        // centers -> registers (shared across items)
        float4 c0 = *reinterpret_cast<const float4*>(P + 64);
        float4 c1 = *reinterpret_cast<const float4*>(P + 68);
        const float ctr[Dsz] = {c0.x, c0.y, c0.z, c0.w, c1.x, c1.y, c1.z, c1.w};

        float xt[ITEMS][Dsz];
#pragma unroll
        for (int it = 0; it < ITEMS; it++)
#pragma unroll
            for (int j = 0; j < Dsz; j++) xt[it][j] = 0.0f;

#pragma unroll
        for (int i = 0; i < Dsz; i++) {
            float4 qa = *reinterpret_cast<const float4*>(P + i * 8);
            float4 qb = *reinterpret_cast<const float4*>(P + i * 8 + 4);
#pragma unroll
            for (int it = 0; it < ITEMS; it++) {
                float xci = xv[it][i] - ctr[i];
                xt[it][0] = fmaf(xci, qa.x, xt[it][0]);
                xt[it][1] = fmaf(xci, qa.y, xt[it][1]);
                xt[it][2] = fmaf(xci, qa.z, xt[it][2]);
                xt[it][3] = fmaf(xci, qa.w, xt[it][3]);
                xt[it][4] = fmaf(xci, qb.x, xt[it][4]);
                xt[it][5] = fmaf(xci, qb.y, xt[it][5]);
                xt[it][6] = fmaf(xci, qb.z, xt[it][6]);
                xt[it][7] = fmaf(xci, qb.w, xt[it][7]);
            }
        }

        float4 l0 = *reinterpret_cast<const float4*>(P + 72);
        float4 l1 = *reinterpret_cast<const float4*>(P + 76);
        float4 n0 = *reinterpret_cast<const float4*>(P + 80);
        float4 n1 = *reinterpret_cast<const float4*>(P + 84);
        const float lc[Dsz] = {l0.x, l0.y, l0.z, l0.w, l1.x, l1.y, l1.z, l1.w};
        const float nb[Dsz] = {n0.x, n0.y, n0.z, n0.w, n1.x, n1.y, n1.z, n1.w};
        const float w = P[88];

#pragma unroll
        for (int it = 0; it < ITEMS; it++) {
            float pk = 1.0f;
#pragma unroll
            for (int j = 0; j < Dsz; j++) {
                float u = xt[it][j] * xt[it][j];
                float v = fmaf(u, nb[j], lc[j]);
                float g = ex2(v) + EPSV;   // c*exp(-0.5 x^2/var) + eps
                pk *= g;
            }
            acc[it] = fmaf(w, pk, acc[it]);
        }
    }

#pragma unroll
    for (int it = 0; it < ITEMS; it++) {
        int b = b0 + it * MTHREADS;
        out[(size_t)b * Tsz + t] = acc[it];
    }
}

// ---------------------------------------------------------------------------
// Launch
// ---------------------------------------------------------------------------
extern "C" void kernel_launch(void* const* d_in, const int* in_sizes, int n_in,
                              void* d_out, int out_size)
{
    const float* x       = (const float*)d_in[0];   // [B,T,D]
    const float* centers = (const float*)d_in[1];   // [T,K,D]
    const float* wlogits = (const float*)d_in[2];   // [T,K]
    const float* logvar  = (const float*)d_in[3];   // [T,K,D]
    const float* covp    = (const float*)d_in[4];   // [T,K,28]
    float* out = (float*)d_out;                     // [B,T]

    precompute_kernel<<<(Tsz * Ksz + 31) / 32, 32>>>(centers, wlogits, logvar, covp);

    dim3 grid(Bsz / (MTHREADS * ITEMS), Tsz);
    main_kernel<<<grid, MTHREADS>>>(x, out);
}

// round 15
// speedup vs baseline: 1.6212x; 1.1936x over previous
#include <cuda_runtime.h>
#include <cuda_bf16.h>
#include <math_constants.h>

// Problem constants (fixed-shape benchmark)
#define Bsz 2048
#define Tsz 512
#define Ksz 8
#define Dsz 8
#define NV  28          // D*(D-1)/2
#define PSTRIDE 92      // floats per (t,k): Q[64] toff[8] lc[8] nb[8] w[1] pad[3]
#define ITEMS 4
#define MTHREADS 128

#define EPSV 1e-7f
#define GAIN 3.5f
#define MAXLV 3.5f
#define LOG2E 1.4426950408889634f

typedef unsigned long long u64;

// Precomputed per-(t,k) parameters: 4096 * 92 * 4B = 1.5 MB scratch
__device__ float g_params[Tsz * Ksz * PSTRIDE];

// ---- packed f32x2 helpers (sm_103a) ---------------------------------------
__device__ __forceinline__ float ex2(float v) {
    float r;
    asm("ex2.approx.ftz.f32 %0, %1;" : "=f"(r) : "f"(v));
    return r;
}
__device__ __forceinline__ u64 ffma2(u64 a, u64 b, u64 c) {
    u64 d;
    asm("fma.rn.f32x2 %0, %1, %2, %3;" : "=l"(d) : "l"(a), "l"(b), "l"(c));
    return d;
}
__device__ __forceinline__ u64 fmul2(u64 a, u64 b) {
    u64 d;
    asm("mul.rn.f32x2 %0, %1, %2;" : "=l"(d) : "l"(a), "l"(b));
    return d;
}
__device__ __forceinline__ u64 pack2(float lo, float hi) {
    u64 d;
    asm("mov.b64 %0, {%1, %2};" : "=l"(d) : "f"(lo), "f"(hi));
    return d;
}
__device__ __forceinline__ void unpack2(u64 v, float& lo, float& hi) {
    asm("mov.b64 {%0, %1}, %2;" : "=f"(lo), "=f"(hi) : "l"(v));
}

// ---------------------------------------------------------------------------
// Kernel 1: per-(t,k) precompute.
//   Q = (I - A)(I + A)^{-1} = 2*(I+A)^{-1} - I    (A antisymmetric)
//   Gauss-Jordan without pivoting is safe (symmetric part of I+A is I).
// Stores Q row-major, the affine offset toff_j = -sum_i ctr_i Q[i][j]
// (folds the center subtraction into the rotation), per-dim
// lc = log2(1/sqrt(2*pi*var)), nb = -0.5*log2(e)/var, and the softmax weight.
// ---------------------------------------------------------------------------
__global__ void __launch_bounds__(32)
precompute_kernel(const float* __restrict__ centers,
                  const float* __restrict__ wlogits,
                  const float* __restrict__ logvar,
                  const float* __restrict__ covp)
{
    int id = blockIdx.x * blockDim.x + threadIdx.x;
    if (id >= Tsz * Ksz) return;
    int t = id / Ksz;
    int k = id - t * Ksz;

    const float* v = covp + id * NV;

    float M[Dsz][Dsz];
    float Inv[Dsz][Dsz];
#pragma unroll
    for (int i = 0; i < Dsz; i++)
#pragma unroll
        for (int j = 0; j < Dsz; j++) {
            M[i][j]   = (i == j) ? 1.0f : 0.0f;
            Inv[i][j] = (i == j) ? 1.0f : 0.0f;
        }
#pragma unroll
    for (int i = 0; i < Dsz; i++) {
#pragma unroll
        for (int j = i + 1; j < Dsz; j++) {
            int f = 8 * i + j;
            float u = (f < NV) ? v[f] : v[55 - f];
            M[i][j] -= 0.5f * u;
            M[j][i] += 0.5f * u;
        }
    }

#pragma unroll
    for (int col = 0; col < Dsz; col++) {
        float piv = 1.0f / M[col][col];
#pragma unroll
        for (int j = 0; j < Dsz; j++) {
            M[col][j]   *= piv;
            Inv[col][j] *= piv;
        }
#pragma unroll
        for (int r = 0; r < Dsz; r++) {
            if (r == col) continue;
            float f2 = M[r][col];
#pragma unroll
            for (int j = 0; j < Dsz; j++) {
                M[r][j]   = fmaf(-f2, M[col][j],   M[r][j]);
                Inv[r][j] = fmaf(-f2, Inv[col][j], Inv[r][j]);
            }
        }
    }

    float* P = g_params + (size_t)id * PSTRIDE;

    // Q = 2*Inv - I, row-major [i][j]
    float Q[Dsz][Dsz];
#pragma unroll
    for (int i = 0; i < Dsz; i++)
#pragma unroll
        for (int j = 0; j < Dsz; j++) {
            Q[i][j] = 2.0f * Inv[i][j] - ((i == j) ? 1.0f : 0.0f);
            P[i * 8 + j] = Q[i][j];
        }

    // toff_j = -sum_i ctr_i * Q[i][j]
    float ctr[Dsz];
#pragma unroll
    for (int d = 0; d < Dsz; d++) ctr[d] = centers[id * Dsz + d];
#pragma unroll
    for (int j = 0; j < Dsz; j++) {
        float s = 0.0f;
#pragma unroll
        for (int i = 0; i < Dsz; i++) s = fmaf(-ctr[i], Q[i][j], s);
        P[64 + j] = s;
    }

#pragma unroll
    for (int d = 0; d < Dsz; d++) {
        float lv = logvar[id * Dsz + d];
        lv = fminf(fmaxf(lv, -MAXLV), MAXLV);
        float var = expf(lv);
        float c = rsqrtf(2.0f * CUDART_PI_F * var);
        P[72 + d] = log2f(c);            // lc
        P[80 + d] = -0.5f * LOG2E / var; // nb
    }

    const float* wl = wlogits + t * Ksz;
    float cl[Ksz];
    float mx = -1e30f;
#pragma unroll
    for (int kk = 0; kk < Ksz; kk++) {
        cl[kk] = fminf(fmaxf(wl[kk], -GAIN), GAIN);
        mx = fmaxf(mx, cl[kk]);
    }
    float sum = 0.0f;
#pragma unroll
    for (int kk = 0; kk < Ksz; kk++) sum += expf(cl[kk] - mx);
    P[88] = expf(cl[k] - mx) / sum;
    P[89] = 0.0f; P[90] = 0.0f; P[91] = 0.0f;
}

// ---------------------------------------------------------------------------
// Kernel 2: main evaluation. ITEMS=4 b-values per thread, one t per block.
// The 8-wide rotate-accumulate runs in packed f32x2 (FFMA2: halves the
// FMA-pipe issue count vs scalar FFMA; rounding identical).
//
// Per (b,t,k):
//   xt = x*Q + toff            (centers pre-folded into toff)
//   p_k = prod_d ( 2^(lc_d + nb_d*xt_d^2) + EPS )
//   p  += w_k * p_k
// ---------------------------------------------------------------------------
__global__ void __launch_bounds__(MTHREADS)
main_kernel(const float* __restrict__ x, float* __restrict__ out)
{
    const int t = blockIdx.y;
    const int tid = threadIdx.x;

    __shared__ float sp[Ksz * PSTRIDE];
    const float* gp = g_params + (size_t)t * Ksz * PSTRIDE;
    for (int i = tid; i < Ksz * PSTRIDE; i += MTHREADS)
        sp[i] = gp[i];
    __syncthreads();

    const int b0 = blockIdx.x * (MTHREADS * ITEMS) + tid;

    // x[b][t][0..7] : 32 bytes, 16B-aligned
    float xv[ITEMS][Dsz];
#pragma unroll
    for (int it = 0; it < ITEMS; it++) {
        int b = b0 + it * MTHREADS;
        const float4* xp = reinterpret_cast<const float4*>(x + ((size_t)b * Tsz + t) * Dsz);
        float4 xa = xp[0];
        float4 xb = xp[1];
        xv[it][0] = xa.x; xv[it][1] = xa.y; xv[it][2] = xa.z; xv[it][3] = xa.w;
        xv[it][4] = xb.x; xv[it][5] = xb.y; xv[it][6] = xb.z; xv[it][7] = xb.w;
    }

    float acc[ITEMS];
#pragma unroll
    for (int it = 0; it < ITEMS; it++) acc[it] = 0.0f;

#pragma unroll
    for (int k = 0; k < Ksz; k++) {
        const float* P = sp + k * PSTRIDE;

        // affine offsets (pairs j01,j23,j45,j67) -> xt init
        ulonglong2 ta = *reinterpret_cast<const ulonglong2*>(P + 64);
        ulonglong2 tb = *reinterpret_cast<const ulonglong2*>(P + 68);

        u64 xt[ITEMS][4];
#pragma unroll
        for (int it = 0; it < ITEMS; it++) {
            xt[it][0] = ta.x; xt[it][1] = ta.y;
            xt[it][2] = tb.x; xt[it][3] = tb.y;
        }

#pragma unroll
        for (int i = 0; i < Dsz; i++) {
            ulonglong2 qa = *reinterpret_cast<const ulonglong2*>(P + i * 8);
            ulonglong2 qb = *reinterpret_cast<const ulonglong2*>(P + i * 8 + 4);
#pragma unroll
            for (int it = 0; it < ITEMS; it++) {
                u64 xp2 = pack2(xv[it][i], xv[it][i]);
                xt[it][0] = ffma2(xp2, qa.x, xt[it][0]);
                xt[it][1] = ffma2(xp2, qa.y, xt[it][1]);
                xt[it][2] = ffma2(xp2, qb.x, xt[it][2]);
                xt[it][3] = ffma2(xp2, qb.y, xt[it][3]);
            }
        }

        ulonglong2 la = *reinterpret_cast<const ulonglong2*>(P + 72);
        ulonglong2 lb = *reinterpret_cast<const ulonglong2*>(P + 76);
        ulonglong2 na = *reinterpret_cast<const ulonglong2*>(P + 80);
        ulonglong2 nb = *reinterpret_cast<const ulonglong2*>(P + 84);
        const float w = P[88];

#pragma unroll
        for (int it = 0; it < ITEMS; it++) {
            // v = lc + nb * xt^2  (packed), then scalar 2^v per dim
            u64 v0 = ffma2(fmul2(xt[it][0], xt[it][0]), na.x, la.x);
            u64 v1 = ffma2(fmul2(xt[it][1], xt[it][1]), na.y, la.y);
            u64 v2 = ffma2(fmul2(xt[it][2], xt[it][2]), nb.x, lb.x);
            u64 v3 = ffma2(fmul2(xt[it][3], xt[it][3]), nb.y, lb.y);

            float s0, s1, s2, s3, s4, s5, s6, s7;
            unpack2(v0, s0, s1);
            unpack2(v1, s2, s3);
            unpack2(v2, s4, s5);
            unpack2(v3, s6, s7);

            float g0 = ex2(s0) + EPSV;
            float g1 = ex2(s1) + EPSV;
            float g2 = ex2(s2) + EPSV;
            float g3 = ex2(s3) + EPSV;
            float g4 = ex2(s4) + EPSV;
            float g5 = ex2(s5) + EPSV;
            float g6 = ex2(s6) + EPSV;
            float g7 = ex2(s7) + EPSV;

            float pk = ((g0 * g1) * (g2 * g3)) * ((g4 * g5) * (g6 * g7));
            acc[it] = fmaf(w, pk, acc[it]);
        }
    }

#pragma unroll
    for (int it = 0; it < ITEMS; it++) {
        int b = b0 + it * MTHREADS;
        out[(size_t)b * Tsz + t] = acc[it];
    }
}

// ---------------------------------------------------------------------------
// Launch
// ---------------------------------------------------------------------------
extern "C" void kernel_launch(void* const* d_in, const int* in_sizes, int n_in,
                              void* d_out, int out_size)
{
    const float* x       = (const float*)d_in[0];   // [B,T,D]
    const float* centers = (const float*)d_in[1];   // [T,K,D]
    const float* wlogits = (const float*)d_in[2];   // [T,K]
    const float* logvar  = (const float*)d_in[3];   // [T,K,D]
    const float* covp    = (const float*)d_in[4];   // [T,K,28]
    float* out = (float*)d_out;                     // [B,T]

    precompute_kernel<<<(Tsz * Ksz + 31) / 32, 32>>>(centers, wlogits, logvar, covp);

    dim3 grid(Bsz / (MTHREADS * ITEMS), Tsz);
    main_kernel<<<grid, MTHREADS>>>(x, out);
}